// round 5
// baseline (speedup 1.0000x reference)
#include <cuda_runtime.h>
#include <cuda_bf16.h>

#define K_NB    10
#define K_TOT   300
#define EV      3      // float4s per smem ctrl entry (2 used + 1 pad => 48B stride)
#define TPB     256
#define BLKS_PER_SM 4
#define NUM_SMS 148

// smem entry layout (per control point j), as float4:
//  [0] = {qw, qx, qy, qz}   normalized ctrl quaternion
//  [1] = {b0, b1, b2, 0}    where b = p + t - rot_q(p)
//  [2] = pad (bank spreading)

__device__ __forceinline__ void quat_rotate(float cw, float cx, float cy, float cz,
                                            float vx, float vy, float vz,
                                            float& ox, float& oy, float& oz)
{
    float tx = cy * vz - cz * vy;
    float ty = cz * vx - cx * vz;
    float tz = cx * vy - cy * vx;
    float ux = cy * tz - cz * ty;
    float uy = cz * tx - cx * tz;
    float uz = cx * ty - cy * tx;
    ox = fmaf(2.f, fmaf(cw, tx, ux), vx);
    oy = fmaf(2.f, fmaf(cw, ty, uy), vy);
    oz = fmaf(2.f, fmaf(cw, tz, uz), vz);
}

__device__ __forceinline__ void finish_and_store(float aq0, float aq1, float aq2, float aq3,
                                                 float4 gq,
                                                 float am0, float am1, float am2,
                                                 float* __restrict__ out_means,
                                                 float* __restrict__ out_quats,
                                                 int i)
{
    float nrm = sqrtf(aq0 * aq0 + aq1 * aq1 + aq2 * aq2 + aq3 * aq3);
    float inv = 1.0f / fmaxf(nrm, 1e-8f);
    float aw = aq0 * inv, ax = aq1 * inv, ay = aq2 * inv, az = aq3 * inv;

    float bw = gq.x, bx = gq.y, by = gq.z, bz = gq.w;
    float4 qo;
    qo.x = aw * bw - ax * bx - ay * by - az * bz;
    qo.y = aw * bx + ax * bw + ay * bz - az * by;
    qo.z = aw * by - ax * bz + ay * bw + az * bx;
    qo.w = aw * bz + ax * by - ay * bx + az * bw;

    out_means[i * 3 + 0] = am0;
    out_means[i * 3 + 1] = am1;
    out_means[i * 3 + 2] = am2;
    reinterpret_cast<float4*>(out_quats)[i] = qo;
}

__global__ __launch_bounds__(TPB, BLKS_PER_SM)
void deform4d_kernel(const float* __restrict__ means,
                     const float* __restrict__ quats,
                     const float* __restrict__ weights,
                     const float* __restrict__ ctrl_trans,
                     const float* __restrict__ ctrl_rots,
                     const float* __restrict__ ctrl_pos,
                     const int*   __restrict__ indices,
                     float* __restrict__ out_means,
                     float* __restrict__ out_quats,
                     int n)
{
    __shared__ float4 s4[K_TOT * EV];

    // ---- build control-point table once per (persistent) block ----
    for (int j = threadIdx.x; j < K_TOT; j += TPB) {
        float4 q = reinterpret_cast<const float4*>(ctrl_rots)[j];
        float nrm = sqrtf(q.x * q.x + q.y * q.y + q.z * q.z + q.w * q.w);
        float inv = 1.0f / fmaxf(nrm, 1e-8f);
        float cw = q.x * inv, cx = q.y * inv, cy = q.z * inv, cz = q.w * inv;

        float px = ctrl_pos[j * 3 + 0];
        float py = ctrl_pos[j * 3 + 1];
        float pz = ctrl_pos[j * 3 + 2];

        float rpx, rpy, rpz;
        quat_rotate(cw, cx, cy, cz, px, py, pz, rpx, rpy, rpz);

        float b0 = px + ctrl_trans[j * 3 + 0] - rpx;
        float b1 = py + ctrl_trans[j * 3 + 1] - rpy;
        float b2 = pz + ctrl_trans[j * 3 + 2] - rpz;

        float4* e = s4 + j * EV;
        e[0] = make_float4(cw, cx, cy, cz);
        e[1] = make_float4(b0, b1, b2, 0.f);
    }
    __syncthreads();

    const int npairs = (n + 1) >> 1;
    const int stride = gridDim.x * TPB;

    for (int p = blockIdx.x * TPB + threadIdx.x; p < npairs; p += stride) {
        const int i0 = 2 * p;
        const int i1 = i0 + 1;
        const bool has1 = (i1 < n);

        // ---- per-pair loads: w/idx are 80B contiguous -> 5x LDG.128 each ----
        float w0[K_NB], w1[K_NB];
        int   j0[K_NB], j1[K_NB];
        {
            const float4* wp = reinterpret_cast<const float4*>(weights + (size_t)i0 * K_NB);
            const int4*   ip = reinterpret_cast<const int4*>(indices + (size_t)i0 * K_NB);
            #pragma unroll
            for (int c = 0; c < 5; c++) {
                float4 tw = wp[c];
                int4   ti = ip[c];
                int base = c * 4;
                float* wd = (base + 0 < K_NB) ? &w0[base] : &w1[base - K_NB];
                // unrolled manual scatter into the two arrays
                if (base + 0 < K_NB) { w0[base + 0] = tw.x; j0[base + 0] = ti.x; } else { w1[base + 0 - K_NB] = tw.x; j1[base + 0 - K_NB] = ti.x; }
                if (base + 1 < K_NB) { w0[base + 1] = tw.y; j0[base + 1] = ti.y; } else { w1[base + 1 - K_NB] = tw.y; j1[base + 1 - K_NB] = ti.y; }
                if (base + 2 < K_NB) { w0[base + 2] = tw.z; j0[base + 2] = ti.z; } else { w1[base + 2 - K_NB] = tw.z; j1[base + 2 - K_NB] = ti.z; }
                if (base + 3 < K_NB) { w0[base + 3] = tw.w; j0[base + 3] = ti.w; } else { w1[base + 3 - K_NB] = tw.w; j1[base + 3 - K_NB] = ti.w; }
                (void)wd;
            }
            if (!has1) {
                #pragma unroll
                for (int k = 0; k < K_NB; k++) { w1[k] = 0.f; j1[k] = 0; }
            }
        }

        // means: 6 consecutive floats (24B, 8B-aligned) -> 3x LDG.64
        float m0x, m0y, m0z, m1x = 0.f, m1y = 0.f, m1z = 0.f;
        {
            const float2* mp = reinterpret_cast<const float2*>(means + (size_t)i0 * 3);
            float2 a = mp[0];
            float2 b = mp[1];
            m0x = a.x; m0y = a.y; m0z = b.x;
            if (has1) {
                float2 c = mp[2];
                m1x = b.y; m1y = c.x; m1z = c.y;
            }
        }

        float4 gq0 = reinterpret_cast<const float4*>(quats)[i0];
        float4 gq1 = has1 ? reinterpret_cast<const float4*>(quats)[i1]
                          : make_float4(0.f, 0.f, 0.f, 0.f);

        // ---- blend both gaussians (interleaved for ILP) ----
        float a0m0 = 0.f, a0m1 = 0.f, a0m2 = 0.f;
        float a0q0 = 0.f, a0q1 = 0.f, a0q2 = 0.f, a0q3 = 0.f;
        float a1m0 = 0.f, a1m1 = 0.f, a1m2 = 0.f;
        float a1q0 = 0.f, a1q1 = 0.f, a1q2 = 0.f, a1q3 = 0.f;

        #pragma unroll
        for (int k = 0; k < K_NB; k++) {
            // gaussian 0
            {
                const float   w = w0[k];
                const float4* e = s4 + j0[k] * EV;
                float4 cq = e[0];
                float4 b  = e[1];
                float vx, vy, vz;
                quat_rotate(cq.x, cq.y, cq.z, cq.w, m0x, m0y, m0z, vx, vy, vz);
                a0m0 = fmaf(w, vx + b.x, a0m0);
                a0m1 = fmaf(w, vy + b.y, a0m1);
                a0m2 = fmaf(w, vz + b.z, a0m2);
                a0q0 = fmaf(w, cq.x, a0q0);
                a0q1 = fmaf(w, cq.y, a0q1);
                a0q2 = fmaf(w, cq.z, a0q2);
                a0q3 = fmaf(w, cq.w, a0q3);
            }
            // gaussian 1
            {
                const float   w = w1[k];
                const float4* e = s4 + j1[k] * EV;
                float4 cq = e[0];
                float4 b  = e[1];
                float vx, vy, vz;
                quat_rotate(cq.x, cq.y, cq.z, cq.w, m1x, m1y, m1z, vx, vy, vz);
                a1m0 = fmaf(w, vx + b.x, a1m0);
                a1m1 = fmaf(w, vy + b.y, a1m1);
                a1m2 = fmaf(w, vz + b.z, a1m2);
                a1q0 = fmaf(w, cq.x, a1q0);
                a1q1 = fmaf(w, cq.y, a1q1);
                a1q2 = fmaf(w, cq.z, a1q2);
                a1q3 = fmaf(w, cq.w, a1q3);
            }
        }

        finish_and_store(a0q0, a0q1, a0q2, a0q3, gq0, a0m0, a0m1, a0m2,
                         out_means, out_quats, i0);
        if (has1) {
            finish_and_store(a1q0, a1q1, a1q2, a1q3, gq1, a1m0, a1m1, a1m2,
                             out_means, out_quats, i1);
        }
    }
}

extern "C" void kernel_launch(void* const* d_in, const int* in_sizes, int n_in,
                              void* d_out, int out_size)
{
    const float* means      = (const float*)d_in[0];
    const float* quats      = (const float*)d_in[1];
    const float* weights    = (const float*)d_in[2];
    const float* ctrl_trans = (const float*)d_in[3];
    const float* ctrl_rots  = (const float*)d_in[4];
    const float* ctrl_pos   = (const float*)d_in[5];
    const int*   indices    = (const int*)d_in[6];

    int n = in_sizes[0] / 3;  // means is [N,3]

    float* out_means = (float*)d_out;
    float* out_quats = (float*)d_out + (size_t)n * 3;

    int npairs = (n + 1) / 2;
    int max_blocks = NUM_SMS * BLKS_PER_SM;
    int need = (npairs + TPB - 1) / TPB;
    int blocks = need < max_blocks ? need : max_blocks;

    deform4d_kernel<<<blocks, TPB>>>(means, quats, weights,
                                     ctrl_trans, ctrl_rots, ctrl_pos,
                                     indices, out_means, out_quats, n);
}

// round 6
// speedup vs baseline: 1.2264x; 1.2264x over previous
#include <cuda_runtime.h>
#include <cuda_bf16.h>

#define K_NB    10
#define K_TOT   300
#define EV      3      // float4s per smem ctrl entry (2 used + 1 pad => 48B stride)
#define TPB     256
#define BLKS_PER_SM 6
#define NUM_SMS 148

// smem entry layout (per control point j), as float4:
//  [0] = {qw, qx, qy, qz}   normalized ctrl quaternion
//  [1] = {b0, b1, b2, 0}    where b = p + t - rot_q(p)
//  [2] = pad (bank spreading)

__device__ __forceinline__ void quat_rotate(float cw, float cx, float cy, float cz,
                                            float vx, float vy, float vz,
                                            float& ox, float& oy, float& oz)
{
    float tx = cy * vz - cz * vy;
    float ty = cz * vx - cx * vz;
    float tz = cx * vy - cy * vx;
    float ux = cy * tz - cz * ty;
    float uy = cz * tx - cx * tz;
    float uz = cx * ty - cy * tx;
    ox = fmaf(2.f, fmaf(cw, tx, ux), vx);
    oy = fmaf(2.f, fmaf(cw, ty, uy), vy);
    oz = fmaf(2.f, fmaf(cw, tz, uz), vz);
}

__global__ __launch_bounds__(TPB, BLKS_PER_SM)
void deform4d_kernel(const float* __restrict__ means,
                     const float* __restrict__ quats,
                     const float* __restrict__ weights,
                     const float* __restrict__ ctrl_trans,
                     const float* __restrict__ ctrl_rots,
                     const float* __restrict__ ctrl_pos,
                     const int*   __restrict__ indices,
                     float* __restrict__ out_means,
                     float* __restrict__ out_quats,
                     int n)
{
    __shared__ float4 s4[K_TOT * EV];

    // ---- build control-point table once per (persistent) block ----
    for (int j = threadIdx.x; j < K_TOT; j += TPB) {
        float4 q = reinterpret_cast<const float4*>(ctrl_rots)[j];
        float nrm = sqrtf(q.x * q.x + q.y * q.y + q.z * q.z + q.w * q.w);
        float inv = 1.0f / fmaxf(nrm, 1e-8f);
        float cw = q.x * inv, cx = q.y * inv, cy = q.z * inv, cz = q.w * inv;

        float px = ctrl_pos[j * 3 + 0];
        float py = ctrl_pos[j * 3 + 1];
        float pz = ctrl_pos[j * 3 + 2];

        float rpx, rpy, rpz;
        quat_rotate(cw, cx, cy, cz, px, py, pz, rpx, rpy, rpz);

        float b0 = px + ctrl_trans[j * 3 + 0] - rpx;
        float b1 = py + ctrl_trans[j * 3 + 1] - rpy;
        float b2 = pz + ctrl_trans[j * 3 + 2] - rpz;

        float4* e = s4 + j * EV;
        e[0] = make_float4(cw, cx, cy, cz);
        e[1] = make_float4(b0, b1, b2, 0.f);
    }
    __syncthreads();

    const int stride = gridDim.x * TPB;

    for (int i = blockIdx.x * TPB + threadIdx.x; i < n; i += stride) {
        // mean (needed throughout the loop)
        float mx = means[i * 3 + 0];
        float my = means[i * 3 + 1];
        float mz = means[i * 3 + 2];

        const float2* wp = reinterpret_cast<const float2*>(weights + (size_t)i * K_NB);
        const int2*   ip = reinterpret_cast<const int2*>(indices + (size_t)i * K_NB);

        float am0 = 0.f, am1 = 0.f, am2 = 0.f;
        float aq0 = 0.f, aq1 = 0.f, aq2 = 0.f, aq3 = 0.f;

        // stream weights/indices in 5 chunks; only one chunk live at a time
        #pragma unroll
        for (int c = 0; c < K_NB / 2; c++) {
            float2 tw = wp[c];
            int2   ti = ip[c];

            {
                const float4* e = s4 + ti.x * EV;
                float4 cq = e[0];
                float4 b  = e[1];
                float vx, vy, vz;
                quat_rotate(cq.x, cq.y, cq.z, cq.w, mx, my, mz, vx, vy, vz);
                am0 = fmaf(tw.x, vx + b.x, am0);
                am1 = fmaf(tw.x, vy + b.y, am1);
                am2 = fmaf(tw.x, vz + b.z, am2);
                aq0 = fmaf(tw.x, cq.x, aq0);
                aq1 = fmaf(tw.x, cq.y, aq1);
                aq2 = fmaf(tw.x, cq.z, aq2);
                aq3 = fmaf(tw.x, cq.w, aq3);
            }
            {
                const float4* e = s4 + ti.y * EV;
                float4 cq = e[0];
                float4 b  = e[1];
                float vx, vy, vz;
                quat_rotate(cq.x, cq.y, cq.z, cq.w, mx, my, mz, vx, vy, vz);
                am0 = fmaf(tw.y, vx + b.x, am0);
                am1 = fmaf(tw.y, vy + b.y, am1);
                am2 = fmaf(tw.y, vz + b.z, am2);
                aq0 = fmaf(tw.y, cq.x, aq0);
                aq1 = fmaf(tw.y, cq.y, aq1);
                aq2 = fmaf(tw.y, cq.z, aq2);
                aq3 = fmaf(tw.y, cq.w, aq3);
            }
        }

        // gaussian quat loaded late — not live during the blend loop
        float4 gq = reinterpret_cast<const float4*>(quats)[i];   // (w,x,y,z)

        // normalize blended quaternion (matches reference eps handling)
        float nrm = sqrtf(aq0 * aq0 + aq1 * aq1 + aq2 * aq2 + aq3 * aq3);
        float inv = 1.0f / fmaxf(nrm, 1e-8f);
        float aw = aq0 * inv, ax = aq1 * inv, ay = aq2 * inv, az = aq3 * inv;

        // Hamilton product: blended * gaussian quat  (w,x,y,z)
        float bw = gq.x, bx = gq.y, by = gq.z, bz = gq.w;
        float4 qo;
        qo.x = aw * bw - ax * bx - ay * by - az * bz;
        qo.y = aw * bx + ax * bw + ay * bz - az * by;
        qo.z = aw * by - ax * bz + ay * bw + az * bx;
        qo.w = aw * bz + ax * by - ay * bx + az * bw;

        out_means[i * 3 + 0] = am0;
        out_means[i * 3 + 1] = am1;
        out_means[i * 3 + 2] = am2;
        reinterpret_cast<float4*>(out_quats)[i] = qo;
    }
}

extern "C" void kernel_launch(void* const* d_in, const int* in_sizes, int n_in,
                              void* d_out, int out_size)
{
    const float* means      = (const float*)d_in[0];
    const float* quats      = (const float*)d_in[1];
    const float* weights    = (const float*)d_in[2];
    const float* ctrl_trans = (const float*)d_in[3];
    const float* ctrl_rots  = (const float*)d_in[4];
    const float* ctrl_pos   = (const float*)d_in[5];
    const int*   indices    = (const int*)d_in[6];

    int n = in_sizes[0] / 3;  // means is [N,3]

    float* out_means = (float*)d_out;
    float* out_quats = (float*)d_out + (size_t)n * 3;

    int max_blocks = NUM_SMS * BLKS_PER_SM;
    int need = (n + TPB - 1) / TPB;
    int blocks = need < max_blocks ? need : max_blocks;

    deform4d_kernel<<<blocks, TPB>>>(means, quats, weights,
                                     ctrl_trans, ctrl_rots, ctrl_pos,
                                     indices, out_means, out_quats, n);
}